// round 10
// baseline (speedup 1.0000x reference)
#include <cuda_runtime.h>
#include <cstdint>
#include <math.h>

// Problem: V=2048, E=512, H=512, L=3, T=512, B=64 -> steps = 511
#define TSTEPS   511
#define NB       64
#define HID      512
#define GATES    2048
#define MREAL    32704            // 511*64
#define MPAD     32768            // padded rows (zeros)
#define VOCAB    2048

// ---------------------------------------------------------------------------
// Static scratch (no allocations anywhere)
// ---------------------------------------------------------------------------
__device__ float g_x [(size_t)MPAD * HID];    //  64 MB layer activations
__device__ float g_xg[(size_t)MPAD * GATES];  // 256 MB input gates / logits stage
__device__ float g_hbuf[2][HID * NB];         // double-buffered h state [col*64+b]
__device__ unsigned g_bar_cnt = 0;            // grid barrier (monotonic gen)
__device__ unsigned g_bar_gen = 0;

// ---------------------------------------------------------------------------
// Embedding gather: x[m][:] = emb[tok[m]][:], zero for pad rows
// ---------------------------------------------------------------------------
__global__ void embed_kernel(const int* __restrict__ tok,
                             const float* __restrict__ emb,
                             float* __restrict__ x)
{
    int idx = blockIdx.x * blockDim.x + threadIdx.x;  // over MPAD*128 float4
    int m  = idx >> 7;
    int e4 = idx & 127;
    float4 v = make_float4(0.f, 0.f, 0.f, 0.f);
    if (m < MREAL) {
        int t = tok[m];
        v = ((const float4*)emb)[(size_t)t * 128 + e4];
    }
    ((float4*)x)[(size_t)m * 128 + e4] = v;
}

// ---------------------------------------------------------------------------
// GEMM + bias: C[m][n] = sum_k A[m][k]*W[n][k] + bias1[n] (+bias2[n])
// A:(MPAD,512) W:(2048,512) C:(*,2048). BM=BN=128, BK=16, 256 thr, 8x8 tile.
// ---------------------------------------------------------------------------
__global__ __launch_bounds__(256, 2)
void gemm_bias(const float* __restrict__ A, const float* __restrict__ W,
               const float* __restrict__ bias1, const float* __restrict__ bias2,
               float* __restrict__ C, int Mguard)
{
    __shared__ float As[16][136];
    __shared__ float Ws[16][136];
    const int tid = threadIdx.x;
    const int tx = tid & 15;          // n-direction
    const int ty = tid >> 4;          // m-direction
    const int n0 = blockIdx.x * 128;
    const int m0 = blockIdx.y * 128;

    float acc[8][8] = {};
    const float* Ap = A + (size_t)m0 * 512;
    const float* Wp = W + (size_t)n0 * 512;

    for (int kb = 0; kb < 512; kb += 16) {
#pragma unroll
        for (int q = 0; q < 2; ++q) {
            int f  = tid + 256 * q;        // 0..511
            int r  = f >> 2;               // row within 128-tile
            int kq = (f & 3) << 2;         // 0,4,8,12
            float4 va = *(const float4*)(Ap + (size_t)r * 512 + kb + kq);
            As[kq + 0][r] = va.x; As[kq + 1][r] = va.y;
            As[kq + 2][r] = va.z; As[kq + 3][r] = va.w;
            float4 vw = *(const float4*)(Wp + (size_t)r * 512 + kb + kq);
            Ws[kq + 0][r] = vw.x; Ws[kq + 1][r] = vw.y;
            Ws[kq + 2][r] = vw.z; Ws[kq + 3][r] = vw.w;
        }
        __syncthreads();
#pragma unroll
        for (int kk = 0; kk < 16; ++kk) {
            float a[8], w[8];
            *(float4*)(a)     = *(const float4*)&As[kk][ty * 8];
            *(float4*)(a + 4) = *(const float4*)&As[kk][ty * 8 + 4];
            *(float4*)(w)     = *(const float4*)&Ws[kk][tx * 8];
            *(float4*)(w + 4) = *(const float4*)&Ws[kk][tx * 8 + 4];
#pragma unroll
            for (int i = 0; i < 8; ++i)
#pragma unroll
                for (int j = 0; j < 8; ++j) acc[i][j] += a[i] * w[j];
        }
        __syncthreads();
    }

    float bb[8];
#pragma unroll
    for (int j = 0; j < 8; ++j) {
        int n = n0 + tx * 8 + j;
        bb[j] = bias1[n] + (bias2 ? bias2[n] : 0.0f);
    }
#pragma unroll
    for (int i = 0; i < 8; ++i) {
        int m = m0 + ty * 8 + i;
        if (m < Mguard) {
            float* cp = C + (size_t)m * 2048 + n0 + tx * 8;
            float4 v0 = make_float4(acc[i][0] + bb[0], acc[i][1] + bb[1],
                                    acc[i][2] + bb[2], acc[i][3] + bb[3]);
            float4 v1 = make_float4(acc[i][4] + bb[4], acc[i][5] + bb[5],
                                    acc[i][6] + bb[6], acc[i][7] + bb[7]);
            *(float4*)cp       = v0;
            *(float4*)(cp + 4) = v1;
        }
    }
}

// ---------------------------------------------------------------------------
// Persistent LSTM layer: 128 blocks x 256 threads, single wave.
// Block bk owns h-cols [bk*4, bk*4+4) and gate rows {j, j+512, j+1024, j+1536}.
// Thread (b = tid&63, jc = tid>>6) computes one (batch, col) cell.
// One grid barrier per step; h double-buffered in g_hbuf.
// Dynamic smem: hs[512*64] ([k*64+b]) + Wsm[16*512] = 160 KB.
// ---------------------------------------------------------------------------
__global__ void lstm_layer(const float* __restrict__ xg,
                           const float* __restrict__ Whh,
                           float* __restrict__ xout)
{
    extern __shared__ float sm[];
    float* hs  = sm;              // [512*64]
    float* Wsm = sm + HID * NB;   // [16*512] layout [(g*4+jc)*512 + k]

    const int tid = threadIdx.x;
    const int b   = tid & 63;
    const int jc  = tid >> 6;
    const int bk  = blockIdx.x;
    const int j   = bk * 4 + jc;

    // Load W_hh slice (gate rows g*512 + bk*4 + jj), vectorized
    for (int idx = tid; idx < 16 * 128; idx += 256) {
        int rl = idx >> 7;            // 0..15 local row
        int k4 = idx & 127;
        int g  = rl >> 2, jj = rl & 3;
        ((float4*)Wsm)[rl * 128 + k4] =
            ((const float4*)Whh)[(size_t)(g * 512 + bk * 4 + jj) * 128 + k4];
    }
    // h0 = 0
    for (int idx = tid; idx < HID * NB / 4; idx += 256)
        ((float4*)hs)[idx] = make_float4(0.f, 0.f, 0.f, 0.f);
    __syncthreads();

    const float* wi = Wsm + (0 * 4 + jc) * 512;
    const float* wf = Wsm + (1 * 4 + jc) * 512;
    const float* wg = Wsm + (2 * 4 + jc) * 512;
    const float* wo = Wsm + (3 * 4 + jc) * 512;

    float c = 0.f;
    for (int t = 0; t < TSTEPS; ++t) {
        size_t base = ((size_t)t * 64 + b) * 2048 + (size_t)j;
        float xi  = xg[base];
        float xf  = xg[base + 512];
        float xgg = xg[base + 1024];
        float xo  = xg[base + 1536];

        float ai = 0.f, af = 0.f, ag = 0.f, ao = 0.f;
#pragma unroll 2
        for (int k4 = 0; k4 < 128; ++k4) {
            float4 vi = ((const float4*)wi)[k4];
            float4 vf = ((const float4*)wf)[k4];
            float4 vg = ((const float4*)wg)[k4];
            float4 vo = ((const float4*)wo)[k4];
            int kb = k4 * 4;
            float h0 = hs[(kb + 0) * 64 + b];
            float h1 = hs[(kb + 1) * 64 + b];
            float h2 = hs[(kb + 2) * 64 + b];
            float h3 = hs[(kb + 3) * 64 + b];
            ai += h0 * vi.x; ai += h1 * vi.y; ai += h2 * vi.z; ai += h3 * vi.w;
            af += h0 * vf.x; af += h1 * vf.y; af += h2 * vf.z; af += h3 * vf.w;
            ag += h0 * vg.x; ag += h1 * vg.y; ag += h2 * vg.z; ag += h3 * vg.w;
            ao += h0 * vo.x; ao += h1 * vo.y; ao += h2 * vo.z; ao += h3 * vo.w;
        }

        float I = 1.f / (1.f + expf(-(xi + ai)));
        float F = 1.f / (1.f + expf(-(xf + af)));
        float G = tanhf(xgg + ag);
        float O = 1.f / (1.f + expf(-(xo + ao)));
        c = F * c + I * G;
        float h = O * tanhf(c);

        xout[((size_t)t * 64 + b) * 512 + j] = h;
        int wb = (t + 1) & 1;
        g_hbuf[wb][j * 64 + b] = h;

        // ---- grid barrier (monotonic generation; replay/launch safe) ----
        __syncthreads();
        if (tid == 0) {
            unsigned gen = *(volatile unsigned*)&g_bar_gen;
            __threadfence();
            if (atomicAdd(&g_bar_cnt, 1u) == gridDim.x - 1u) {
                g_bar_cnt = 0;
                __threadfence();
                *(volatile unsigned*)&g_bar_gen = gen + 1u;
            } else {
                while (*(volatile unsigned*)&g_bar_gen == gen) { }
            }
            __threadfence();
        }
        __syncthreads();

        // reload full h into smem from the buffer written this step
        const float4* src = (const float4*)g_hbuf[wb];
        for (int idx = tid; idx < HID * NB / 4; idx += 256)
            ((float4*)hs)[idx] = src[idx];
        __syncthreads();
    }
}

// ---------------------------------------------------------------------------
// threefry2x32 (JAX), key = (0, 1)
// ---------------------------------------------------------------------------
__device__ __forceinline__ void threefry01(uint32_t x0, uint32_t x1,
                                           uint32_t& o0, uint32_t& o1)
{
    const uint32_t k0 = 0u, k1 = 1u;
    const uint32_t k2 = 0x1BD11BDAu ^ k0 ^ k1;   // 0x1BD11BDB
    x0 += k0; x1 += k1;
#define TFR(r) { x0 += x1; x1 = (x1 << (r)) | (x1 >> (32 - (r))); x1 ^= x0; }
    TFR(13) TFR(15) TFR(26) TFR(6)
    x0 += k1; x1 += k2 + 1u;
    TFR(17) TFR(29) TFR(16) TFR(24)
    x0 += k2; x1 += k0 + 2u;
    TFR(13) TFR(15) TFR(26) TFR(6)
    x0 += k0; x1 += k1 + 3u;
    TFR(17) TFR(29) TFR(16) TFR(24)
    x0 += k1; x1 += k2 + 4u;
    TFR(13) TFR(15) TFR(26) TFR(6)
    x0 += k2; x1 += k0 + 5u;
#undef TFR
    o0 = x0; o1 = x1;
}

// JAX gumbel: u = bitcast(bits>>9 | 0x3f800000) - 1; u = max(u, tiny);
// g = -log(-log(u)).  Accurate logf required (fast-log tail error flips argmax).
__device__ __forceinline__ float gumbelf(uint32_t bits)
{
    float u = __uint_as_float((bits >> 9) | 0x3f800000u) - 1.0f;
    u = fmaxf(u, 1.17549435e-38f);
    return -logf(-logf(u));
}

// Partitionable threefry random_bits (jax/_src/prng.py):
//   counts_hi, counts_lo = iota_2x32_shape(shape)      (hi = 0 for size < 2^32)
//   bits1, bits2 = threefry2x32(key, counts_hi, counts_lo)
//   bit_width == 64: (bits1 << 32) | bits2
//   bit_width <  64: convert(bits1 ^ bits2)            <-- XOR of both words
// So for 32-bit draws: bits[i] = o0 ^ o1 of threefry((0,1), 0, i).
// One block per (t,b) row; 256 threads scan the 2048-vocab gumbel-argmax.
__global__ void sample_kernel(const float* __restrict__ logits,
                              float* outF, int* outI, int asInt)
{
    const int r = blockIdx.x;
    const int tid = threadIdx.x;

    float best = -3.4e38f;
    int bidx = 0;
    for (int v = tid; v < VOCAB; v += 256) {
        uint32_t i = (uint32_t)r * 2048u + (uint32_t)v;   // linear index < 2^32
        uint32_t o0, o1;
        threefry01(0u, i, o0, o1);
        float val = logits[(size_t)r * 2048 + v] + gumbelf(o0 ^ o1);
        if (val > best) { best = val; bidx = v; }   // strided v increasing -> first idx
    }

    __shared__ float svv[256];
    __shared__ int   sii[256];
    svv[tid] = best; sii[tid] = bidx;
    __syncthreads();
    for (int s = 128; s > 0; s >>= 1) {
        if (tid < s) {
            float v2 = svv[tid + s]; int i2 = sii[tid + s];
            float v1 = svv[tid];     int i1 = sii[tid];
            if (v2 > v1 || (v2 == v1 && i2 < i1)) { svv[tid] = v2; sii[tid] = i2; }
        }
        __syncthreads();
    }
    if (tid == 0) {
        if (asInt) outI[r] = sii[0];
        else       outF[r] = (float)sii[0];
    }
}

// ---------------------------------------------------------------------------
// Launch
// ---------------------------------------------------------------------------
extern "C" void kernel_launch(void* const* d_in, const int* in_sizes, int n_in,
                              void* d_out, int out_size)
{
    const int*   tok  = (const int*)  d_in[0];
    const float* emb  = (const float*)d_in[1];
    const float* Wih  = (const float*)d_in[2];
    const float* Whh  = (const float*)d_in[3];
    const float* bih  = (const float*)d_in[4];
    const float* bhh  = (const float*)d_in[5];
    const float* Wout = (const float*)d_in[6];
    const float* bout = (const float*)d_in[7];

    void* p;
    cudaGetSymbolAddress(&p, g_x);   float* xbuf  = (float*)p;
    cudaGetSymbolAddress(&p, g_xg);  float* xgbuf = (float*)p;

    cudaFuncSetAttribute(lstm_layer,
                         cudaFuncAttributeMaxDynamicSharedMemorySize, 164 * 1024);

    embed_kernel<<<MPAD * 128 / 256, 256>>>(tok, emb, xbuf);

    dim3 gg(GATES / 128, MPAD / 128);
    for (int l = 0; l < 3; ++l) {
        gemm_bias<<<gg, 256>>>(xbuf, Wih + (size_t)l * GATES * HID,
                               bih + l * GATES, bhh + l * GATES, xgbuf, MPAD);
        lstm_layer<<<128, 256, 163840>>>(xgbuf, Whh + (size_t)l * GATES * HID, xbuf);
    }

    // Output dispatch: tuple (indices, logits) flattened is the expected case.
    float* logitsPtr;
    int mode;                               // 0 full, 1 logits-only, 2 int idx
    if (out_size == MREAL + MREAL * VOCAB) { mode = 0; logitsPtr = (float*)d_out + MREAL; }
    else if (out_size == MREAL)            { mode = 2; logitsPtr = xgbuf; }
    else                                   { mode = 1; logitsPtr = (float*)d_out; }

    gemm_bias<<<gg, 256>>>(xbuf, Wout, bout, nullptr, logitsPtr, MREAL);

    if (mode == 0)
        sample_kernel<<<MREAL, 256>>>(logitsPtr, (float*)d_out, nullptr, 0);
    else if (mode == 2)
        sample_kernel<<<MREAL, 256>>>(logitsPtr, nullptr, (int*)d_out, 1);
}

// round 13
// speedup vs baseline: 1.0503x; 1.0503x over previous
#include <cuda_runtime.h>
#include <cstdint>
#include <math.h>

// Problem: V=2048, E=512, H=512, L=3, T=512, B=64 -> steps = 511
#define TSTEPS   511
#define NB       64
#define HID      512
#define GATES    2048
#define MREAL    32704            // 511*64
#define MPAD     32768            // padded rows (zeros)
#define VOCAB    2048

typedef unsigned long long ull;

// ---------------------------------------------------------------------------
// Packed f32x2 helpers (sm_103a): one issue slot = two IEEE fp32 FMAs.
// ---------------------------------------------------------------------------
__device__ __forceinline__ void ffma2(ull& d, ull a, ull b) {
    asm("fma.rn.f32x2 %0, %1, %2, %0;" : "+l"(d) : "l"(a), "l"(b));
}
__device__ __forceinline__ ull pk(float x, float y) {
    ull r; asm("mov.b64 %0, {%1, %2};" : "=l"(r) : "f"(x), "f"(y)); return r;
}
__device__ __forceinline__ float2 unpk(ull p) {
    float x, y; asm("mov.b64 {%0, %1}, %2;" : "=f"(x), "=f"(y) : "l"(p));
    return make_float2(x, y);
}
__device__ __forceinline__ float psum(ull p) {
    float2 v = unpk(p); return v.x + v.y;
}

// ---------------------------------------------------------------------------
// Static scratch (no allocations anywhere)
// ---------------------------------------------------------------------------
__device__ float g_x [(size_t)MPAD * HID];    //  64 MB layer activations
__device__ float g_xg[(size_t)MPAD * GATES];  // 256 MB input gates / logits stage
__device__ float g_hbuf[2][HID * NB];         // double-buffered h, pair-interleaved
__device__ unsigned g_bar_cnt = 0;            // grid barrier (monotonic gen)
__device__ unsigned g_bar_gen = 0;

// ---------------------------------------------------------------------------
// Embedding gather: x[m][:] = emb[tok[m]][:], zero for pad rows
// ---------------------------------------------------------------------------
__global__ void embed_kernel(const int* __restrict__ tok,
                             const float* __restrict__ emb,
                             float* __restrict__ x)
{
    int idx = blockIdx.x * blockDim.x + threadIdx.x;  // over MPAD*128 float4
    int m  = idx >> 7;
    int e4 = idx & 127;
    float4 v = make_float4(0.f, 0.f, 0.f, 0.f);
    if (m < MREAL) {
        int t = tok[m];
        v = ((const float4*)emb)[(size_t)t * 128 + e4];
    }
    ((float4*)x)[(size_t)m * 128 + e4] = v;
}

// ---------------------------------------------------------------------------
// GEMM + bias: C[m][n] = sum_k A[m][k]*W[n][k] + bias1[n] (+bias2[n])
// A:(MPAD,512) W:(2048,512) C:(*,2048). BM=BN=128, BK=16, 256 thr, 8x8 tile.
// Packed f32x2 accumulators over j-pairs; register prefetch of next k-tile.
// Stride 136 floats = 544 B: 16B-aligned rows (LDS.128-legal), same layout
// that passed at 27.3 ms.
// ---------------------------------------------------------------------------
__global__ __launch_bounds__(256, 2)
void gemm_bias(const float* __restrict__ A, const float* __restrict__ W,
               const float* __restrict__ bias1, const float* __restrict__ bias2,
               float* __restrict__ C, int Mguard)
{
    __shared__ float As[16][136];
    __shared__ float Ws[16][136];
    const int tid = threadIdx.x;
    const int tx = tid & 15;          // n-direction
    const int ty = tid >> 4;          // m-direction
    const int n0 = blockIdx.x * 128;
    const int m0 = blockIdx.y * 128;

    ull acc2[8][4];
#pragma unroll
    for (int i = 0; i < 8; ++i)
#pragma unroll
        for (int jp = 0; jp < 4; ++jp) acc2[i][jp] = 0ull;

    const float* Ap = A + (size_t)m0 * 512;
    const float* Wp = W + (size_t)n0 * 512;

    const int r0  = tid >> 2;             // row in tile for load slot q=0
    const int r1  = (tid + 256) >> 2;     //                    slot q=1
    const int kq0 = (tid & 3) << 2;

    // preload k-tile 0 into registers
    float4 pa0 = *(const float4*)(Ap + (size_t)r0 * 512 + kq0);
    float4 pa1 = *(const float4*)(Ap + (size_t)r1 * 512 + kq0);
    float4 pw0 = *(const float4*)(Wp + (size_t)r0 * 512 + kq0);
    float4 pw1 = *(const float4*)(Wp + (size_t)r1 * 512 + kq0);

    for (int kb = 0; kb < 512; kb += 16) {
        // stage registers -> smem (transposed)
        As[kq0 + 0][r0] = pa0.x; As[kq0 + 1][r0] = pa0.y;
        As[kq0 + 2][r0] = pa0.z; As[kq0 + 3][r0] = pa0.w;
        As[kq0 + 0][r1] = pa1.x; As[kq0 + 1][r1] = pa1.y;
        As[kq0 + 2][r1] = pa1.z; As[kq0 + 3][r1] = pa1.w;
        Ws[kq0 + 0][r0] = pw0.x; Ws[kq0 + 1][r0] = pw0.y;
        Ws[kq0 + 2][r0] = pw0.z; Ws[kq0 + 3][r0] = pw0.w;
        Ws[kq0 + 0][r1] = pw1.x; Ws[kq0 + 1][r1] = pw1.y;
        Ws[kq0 + 2][r1] = pw1.z; Ws[kq0 + 3][r1] = pw1.w;
        __syncthreads();

        // prefetch next k-tile while computing this one
        if (kb + 16 < 512) {
            int kn = kb + 16 + kq0;
            pa0 = *(const float4*)(Ap + (size_t)r0 * 512 + kn);
            pa1 = *(const float4*)(Ap + (size_t)r1 * 512 + kn);
            pw0 = *(const float4*)(Wp + (size_t)r0 * 512 + kn);
            pw1 = *(const float4*)(Wp + (size_t)r1 * 512 + kn);
        }

#pragma unroll
        for (int kk = 0; kk < 16; ++kk) {
            float4 a0 = *(const float4*)&As[kk][ty * 8];
            float4 a1 = *(const float4*)&As[kk][ty * 8 + 4];
            float4 w0 = *(const float4*)&Ws[kk][tx * 8];
            float4 w1 = *(const float4*)&Ws[kk][tx * 8 + 4];
            ull wp[4] = { pk(w0.x, w0.y), pk(w0.z, w0.w),
                          pk(w1.x, w1.y), pk(w1.z, w1.w) };
            ull ad[8] = { pk(a0.x, a0.x), pk(a0.y, a0.y),
                          pk(a0.z, a0.z), pk(a0.w, a0.w),
                          pk(a1.x, a1.x), pk(a1.y, a1.y),
                          pk(a1.z, a1.z), pk(a1.w, a1.w) };
#pragma unroll
            for (int i = 0; i < 8; ++i)
#pragma unroll
                for (int jp = 0; jp < 4; ++jp)
                    ffma2(acc2[i][jp], ad[i], wp[jp]);
        }
        __syncthreads();
    }

    float bb[8];
#pragma unroll
    for (int j = 0; j < 8; ++j) {
        int n = n0 + tx * 8 + j;
        bb[j] = bias1[n] + (bias2 ? bias2[n] : 0.0f);
    }
#pragma unroll
    for (int i = 0; i < 8; ++i) {
        int m = m0 + ty * 8 + i;
        if (m < Mguard) {
            float* cp = C + (size_t)m * 2048 + n0 + tx * 8;
            float2 p0 = unpk(acc2[i][0]), p1 = unpk(acc2[i][1]);
            float2 p2 = unpk(acc2[i][2]), p3 = unpk(acc2[i][3]);
            float4 v0 = make_float4(p0.x + bb[0], p0.y + bb[1],
                                    p1.x + bb[2], p1.y + bb[3]);
            float4 v1 = make_float4(p2.x + bb[4], p2.y + bb[5],
                                    p3.x + bb[6], p3.y + bb[7]);
            *(float4*)cp       = v0;
            *(float4*)(cp + 4) = v1;
        }
    }
}

// ---------------------------------------------------------------------------
// Persistent LSTM layer: 128 blocks x 256 threads, single wave.
// Block bk owns h-cols [bk*4, bk*4+4) and gate rows {j, j+512, j+1024, j+1536}.
// Thread (b = tid&63, jc = tid>>6) computes one (batch, col) cell.
// h stored PAIR-INTERLEAVED: hs[(k/2)*128 + b*2 + (k&1)] so an h-pair is one
// LDS.64; w pairs come free from float4 regs; dots use packed fma.rn.f32x2.
// One grid barrier per step; h double-buffered in g_hbuf (same layout).
// Dynamic smem: hs[512*64] + Wsm[16*512] = 160 KB.
// ---------------------------------------------------------------------------
__global__ void lstm_layer(const float* __restrict__ xg,
                           const float* __restrict__ Whh,
                           float* __restrict__ xout)
{
    extern __shared__ float sm[];
    float* hs  = sm;              // [512*64] pair-interleaved
    float* Wsm = sm + HID * NB;   // [16*512] layout [(g*4+jc)*512 + k]

    const int tid = threadIdx.x;
    const int b   = tid & 63;
    const int jc  = tid >> 6;
    const int bk  = blockIdx.x;
    const int j   = bk * 4 + jc;

    // Load W_hh slice (gate rows g*512 + bk*4 + jj), vectorized
    for (int idx = tid; idx < 16 * 128; idx += 256) {
        int rl = idx >> 7;            // 0..15 local row
        int k4 = idx & 127;
        int g  = rl >> 2, jj = rl & 3;
        ((float4*)Wsm)[rl * 128 + k4] =
            ((const float4*)Whh)[(size_t)(g * 512 + bk * 4 + jj) * 128 + k4];
    }
    // h0 = 0
    for (int idx = tid; idx < HID * NB / 4; idx += 256)
        ((float4*)hs)[idx] = make_float4(0.f, 0.f, 0.f, 0.f);
    __syncthreads();

    const float* wi = Wsm + (0 * 4 + jc) * 512;
    const float* wf = Wsm + (1 * 4 + jc) * 512;
    const float* wg = Wsm + (2 * 4 + jc) * 512;
    const float* wo = Wsm + (3 * 4 + jc) * 512;
    const ull* hp = (const ull*)hs;   // hp[t2*64 + b] = (h[2t2], h[2t2+1])

    // h write target (pair-interleaved): [(j>>1)*128 + b*2 + (j&1)]
    const int hoff = (j >> 1) * 128 + b * 2 + (j & 1);

    float c = 0.f;
    for (int t = 0; t < TSTEPS; ++t) {
        size_t base = ((size_t)t * 64 + b) * 2048 + (size_t)j;
        float xi  = xg[base];
        float xf  = xg[base + 512];
        float xgg = xg[base + 1024];
        float xo  = xg[base + 1536];

        ull ai2 = 0ull, af2 = 0ull, ag2 = 0ull, ao2 = 0ull;
#pragma unroll 4
        for (int k4 = 0; k4 < 128; ++k4) {
            float4 vi = ((const float4*)wi)[k4];
            float4 vf = ((const float4*)wf)[k4];
            float4 vg = ((const float4*)wg)[k4];
            float4 vo = ((const float4*)wo)[k4];
            ull h01 = hp[(2 * k4) * 64 + b];        // (h[4k4],   h[4k4+1])
            ull h23 = hp[(2 * k4 + 1) * 64 + b];    // (h[4k4+2], h[4k4+3])
            ffma2(ai2, h01, pk(vi.x, vi.y)); ffma2(ai2, h23, pk(vi.z, vi.w));
            ffma2(af2, h01, pk(vf.x, vf.y)); ffma2(af2, h23, pk(vf.z, vf.w));
            ffma2(ag2, h01, pk(vg.x, vg.y)); ffma2(ag2, h23, pk(vg.z, vg.w));
            ffma2(ao2, h01, pk(vo.x, vo.y)); ffma2(ao2, h23, pk(vo.z, vo.w));
        }
        float ai = psum(ai2), af = psum(af2), ag = psum(ag2), ao = psum(ao2);

        float I = 1.f / (1.f + expf(-(xi + ai)));
        float F = 1.f / (1.f + expf(-(xf + af)));
        float G = tanhf(xgg + ag);
        float O = 1.f / (1.f + expf(-(xo + ao)));
        c = F * c + I * G;
        float h = O * tanhf(c);

        xout[((size_t)t * 64 + b) * 512 + j] = h;
        int wb = (t + 1) & 1;
        g_hbuf[wb][hoff] = h;

        // ---- grid barrier (monotonic generation; replay/launch safe) ----
        __syncthreads();
        if (tid == 0) {
            unsigned gen = *(volatile unsigned*)&g_bar_gen;
            __threadfence();
            if (atomicAdd(&g_bar_cnt, 1u) == gridDim.x - 1u) {
                g_bar_cnt = 0;
                __threadfence();
                *(volatile unsigned*)&g_bar_gen = gen + 1u;
            } else {
                while (*(volatile unsigned*)&g_bar_gen == gen) { }
            }
            __threadfence();
        }
        __syncthreads();

        // reload full h into smem (same pair-interleaved layout: straight copy)
        const float4* src = (const float4*)g_hbuf[wb];
        for (int idx = tid; idx < HID * NB / 4; idx += 256)
            ((float4*)hs)[idx] = src[idx];
        __syncthreads();
    }
}

// ---------------------------------------------------------------------------
// threefry2x32 (JAX), key = (0, 1)
// ---------------------------------------------------------------------------
__device__ __forceinline__ void threefry01(uint32_t x0, uint32_t x1,
                                           uint32_t& o0, uint32_t& o1)
{
    const uint32_t k0 = 0u, k1 = 1u;
    const uint32_t k2 = 0x1BD11BDAu ^ k0 ^ k1;   // 0x1BD11BDB
    x0 += k0; x1 += k1;
#define TFR(r) { x0 += x1; x1 = (x1 << (r)) | (x1 >> (32 - (r))); x1 ^= x0; }
    TFR(13) TFR(15) TFR(26) TFR(6)
    x0 += k1; x1 += k2 + 1u;
    TFR(17) TFR(29) TFR(16) TFR(24)
    x0 += k2; x1 += k0 + 2u;
    TFR(13) TFR(15) TFR(26) TFR(6)
    x0 += k0; x1 += k1 + 3u;
    TFR(17) TFR(29) TFR(16) TFR(24)
    x0 += k1; x1 += k2 + 4u;
    TFR(13) TFR(15) TFR(26) TFR(6)
    x0 += k2; x1 += k0 + 5u;
#undef TFR
    o0 = x0; o1 = x1;
}

// JAX gumbel: u = bitcast(bits>>9 | 0x3f800000) - 1; u = max(u, tiny);
// g = -log(-log(u)).  Accurate logf required (fast-log tail error flips argmax).
__device__ __forceinline__ float gumbelf(uint32_t bits)
{
    float u = __uint_as_float((bits >> 9) | 0x3f800000u) - 1.0f;
    u = fmaxf(u, 1.17549435e-38f);
    return -logf(-logf(u));
}

// Partitionable threefry random_bits (jax/_src/prng.py):
//   bits1, bits2 = threefry2x32(key, counts_hi=0, counts_lo=i)
//   bit_width < 64: convert(bits1 ^ bits2)   <-- XOR of both output words
// One block per (t,b) row; 256 threads scan the 2048-vocab gumbel-argmax.
__global__ void sample_kernel(const float* __restrict__ logits,
                              float* outF, int* outI, int asInt)
{
    const int r = blockIdx.x;
    const int tid = threadIdx.x;

    float best = -3.4e38f;
    int bidx = 0;
    for (int v = tid; v < VOCAB; v += 256) {
        uint32_t i = (uint32_t)r * 2048u + (uint32_t)v;   // linear index < 2^32
        uint32_t o0, o1;
        threefry01(0u, i, o0, o1);
        float val = logits[(size_t)r * 2048 + v] + gumbelf(o0 ^ o1);
        if (val > best) { best = val; bidx = v; }   // strided v increasing -> first idx
    }

    __shared__ float svv[256];
    __shared__ int   sii[256];
    svv[tid] = best; sii[tid] = bidx;
    __syncthreads();
    for (int s = 128; s > 0; s >>= 1) {
        if (tid < s) {
            float v2 = svv[tid + s]; int i2 = sii[tid + s];
            float v1 = svv[tid];     int i1 = sii[tid];
            if (v2 > v1 || (v2 == v1 && i2 < i1)) { svv[tid] = v2; sii[tid] = i2; }
        }
        __syncthreads();
    }
    if (tid == 0) {
        if (asInt) outI[r] = sii[0];
        else       outF[r] = (float)sii[0];
    }
}

// ---------------------------------------------------------------------------
// Launch
// ---------------------------------------------------------------------------
extern "C" void kernel_launch(void* const* d_in, const int* in_sizes, int n_in,
                              void* d_out, int out_size)
{
    const int*   tok  = (const int*)  d_in[0];
    const float* emb  = (const float*)d_in[1];
    const float* Wih  = (const float*)d_in[2];
    const float* Whh  = (const float*)d_in[3];
    const float* bih  = (const float*)d_in[4];
    const float* bhh  = (const float*)d_in[5];
    const float* Wout = (const float*)d_in[6];
    const float* bout = (const float*)d_in[7];

    void* p;
    cudaGetSymbolAddress(&p, g_x);   float* xbuf  = (float*)p;
    cudaGetSymbolAddress(&p, g_xg);  float* xgbuf = (float*)p;

    cudaFuncSetAttribute(lstm_layer,
                         cudaFuncAttributeMaxDynamicSharedMemorySize, 164 * 1024);

    embed_kernel<<<MPAD * 128 / 256, 256>>>(tok, emb, xbuf);

    dim3 gg(GATES / 128, MPAD / 128);
    for (int l = 0; l < 3; ++l) {
        gemm_bias<<<gg, 256>>>(xbuf, Wih + (size_t)l * GATES * HID,
                               bih + l * GATES, bhh + l * GATES, xgbuf, MPAD);
        lstm_layer<<<128, 256, 163840>>>(xgbuf, Whh + (size_t)l * GATES * HID, xbuf);
    }

    // Output dispatch: tuple (indices, logits) flattened is the expected case.
    float* logitsPtr;
    int mode;                               // 0 full, 1 logits-only, 2 int idx
    if (out_size == MREAL + MREAL * VOCAB) { mode = 0; logitsPtr = (float*)d_out + MREAL; }
    else if (out_size == MREAL)            { mode = 2; logitsPtr = xgbuf; }
    else                                   { mode = 1; logitsPtr = (float*)d_out; }

    gemm_bias<<<gg, 256>>>(xbuf, Wout, bout, nullptr, logitsPtr, MREAL);

    if (mode == 0)
        sample_kernel<<<MREAL, 256>>>(logitsPtr, (float*)d_out, nullptr, 0);
    else if (mode == 2)
        sample_kernel<<<MREAL, 256>>>(logitsPtr, nullptr, (int*)d_out, 1);
}

// round 14
// speedup vs baseline: 1.0526x; 1.0023x over previous
#include <cuda_runtime.h>
#include <cstdint>
#include <math.h>

// Problem: V=2048, E=512, H=512, L=3, T=512, B=64 -> steps = 511
#define TSTEPS   511
#define NB       64
#define HID      512
#define GATES    2048
#define MREAL    32704            // 511*64
#define MPAD     32768            // padded rows (zeros)
#define VOCAB    2048

typedef unsigned long long ull;

// ---------------------------------------------------------------------------
// Packed f32x2 helpers (sm_103a). NOTE (R13 finding): FFMA2 = 2 fma-pipe
// passes (throughput-neutral vs 2xFFMA) but halves issue slots.
// ---------------------------------------------------------------------------
__device__ __forceinline__ void ffma2(ull& d, ull a, ull b) {
    asm("fma.rn.f32x2 %0, %1, %2, %0;" : "+l"(d) : "l"(a), "l"(b));
}
__device__ __forceinline__ ull pk(float x, float y) {
    ull r; asm("mov.b64 %0, {%1, %2};" : "=l"(r) : "f"(x), "f"(y)); return r;
}
__device__ __forceinline__ float2 unpk(ull p) {
    float x, y; asm("mov.b64 {%0, %1}, %2;" : "=f"(x), "=f"(y) : "l"(p));
    return make_float2(x, y);
}
__device__ __forceinline__ float psum(ull p) {
    float2 v = unpk(p); return v.x + v.y;
}

// ---------------------------------------------------------------------------
// Static scratch (no allocations anywhere)
// ---------------------------------------------------------------------------
__device__ float g_x [(size_t)MPAD * HID];    //  64 MB layer activations
__device__ float g_xg[(size_t)MPAD * GATES];  // 256 MB input gates / logits stage
__device__ float g_hbuf[2][HID * NB];         // double-buffered h, pair-interleaved
__device__ unsigned g_bar_cnt = 0;            // grid barrier (monotonic gen)
__device__ unsigned g_bar_gen = 0;

// ---------------------------------------------------------------------------
// Embedding gather: x[m][:] = emb[tok[m]][:], zero for pad rows
// ---------------------------------------------------------------------------
__global__ void embed_kernel(const int* __restrict__ tok,
                             const float* __restrict__ emb,
                             float* __restrict__ x)
{
    int idx = blockIdx.x * blockDim.x + threadIdx.x;  // over MPAD*128 float4
    int m  = idx >> 7;
    int e4 = idx & 127;
    float4 v = make_float4(0.f, 0.f, 0.f, 0.f);
    if (m < MREAL) {
        int t = tok[m];
        v = ((const float4*)emb)[(size_t)t * 128 + e4];
    }
    ((float4*)x)[(size_t)m * 128 + e4] = v;
}

// ---------------------------------------------------------------------------
// GEMM + bias: C[m][n] = sum_k A[m][k]*W[n][k] + bias1[n] (+bias2[n])
// A:(MPAD,512) W:(2048,512) C:(*,2048). BM=BN=128, BK=16, 256 thr, 8x8 tile.
// DOUBLE-BUFFERED smem (one __syncthreads per k-tile, LDG overlapped with
// compute). Packed f32x2 accumulators. Stride 136 floats (16B-aligned rows).
// ---------------------------------------------------------------------------
__global__ __launch_bounds__(256, 2)
void gemm_bias(const float* __restrict__ A, const float* __restrict__ W,
               const float* __restrict__ bias1, const float* __restrict__ bias2,
               float* __restrict__ C, int Mguard)
{
    __shared__ float As[2][16][136];
    __shared__ float Ws[2][16][136];
    const int tid = threadIdx.x;
    const int tx = tid & 15;          // n-direction
    const int ty = tid >> 4;          // m-direction
    const int n0 = blockIdx.x * 128;
    const int m0 = blockIdx.y * 128;

    ull acc2[8][4];
#pragma unroll
    for (int i = 0; i < 8; ++i)
#pragma unroll
        for (int jp = 0; jp < 4; ++jp) acc2[i][jp] = 0ull;

    const float* Ap = A + (size_t)m0 * 512;
    const float* Wp = W + (size_t)n0 * 512;

    const int r0  = tid >> 2;             // row in tile for load slot q=0
    const int r1  = (tid + 256) >> 2;     //                    slot q=1
    const int kq0 = (tid & 3) << 2;

    // preload k-tile 0 into registers and stage into buffer 0
    float4 pa0 = *(const float4*)(Ap + (size_t)r0 * 512 + kq0);
    float4 pa1 = *(const float4*)(Ap + (size_t)r1 * 512 + kq0);
    float4 pw0 = *(const float4*)(Wp + (size_t)r0 * 512 + kq0);
    float4 pw1 = *(const float4*)(Wp + (size_t)r1 * 512 + kq0);

    As[0][kq0 + 0][r0] = pa0.x; As[0][kq0 + 1][r0] = pa0.y;
    As[0][kq0 + 2][r0] = pa0.z; As[0][kq0 + 3][r0] = pa0.w;
    As[0][kq0 + 0][r1] = pa1.x; As[0][kq0 + 1][r1] = pa1.y;
    As[0][kq0 + 2][r1] = pa1.z; As[0][kq0 + 3][r1] = pa1.w;
    Ws[0][kq0 + 0][r0] = pw0.x; Ws[0][kq0 + 1][r0] = pw0.y;
    Ws[0][kq0 + 2][r0] = pw0.z; Ws[0][kq0 + 3][r0] = pw0.w;
    Ws[0][kq0 + 0][r1] = pw1.x; Ws[0][kq0 + 1][r1] = pw1.y;
    Ws[0][kq0 + 2][r1] = pw1.z; Ws[0][kq0 + 3][r1] = pw1.w;
    __syncthreads();

    for (int it = 0; it < 32; ++it) {
        const int cur = it & 1;
        const int nxt = cur ^ 1;

        // prefetch next k-tile (overlapped with compute below)
        if (it < 31) {
            int kn = (it + 1) * 16 + kq0;
            pa0 = *(const float4*)(Ap + (size_t)r0 * 512 + kn);
            pa1 = *(const float4*)(Ap + (size_t)r1 * 512 + kn);
            pw0 = *(const float4*)(Wp + (size_t)r0 * 512 + kn);
            pw1 = *(const float4*)(Wp + (size_t)r1 * 512 + kn);
        }

#pragma unroll
        for (int kk = 0; kk < 16; ++kk) {
            float4 a0 = *(const float4*)&As[cur][kk][ty * 8];
            float4 a1 = *(const float4*)&As[cur][kk][ty * 8 + 4];
            float4 w0 = *(const float4*)&Ws[cur][kk][tx * 8];
            float4 w1 = *(const float4*)&Ws[cur][kk][tx * 8 + 4];
            ull wp[4] = { pk(w0.x, w0.y), pk(w0.z, w0.w),
                          pk(w1.x, w1.y), pk(w1.z, w1.w) };
            ull ad[8] = { pk(a0.x, a0.x), pk(a0.y, a0.y),
                          pk(a0.z, a0.z), pk(a0.w, a0.w),
                          pk(a1.x, a1.x), pk(a1.y, a1.y),
                          pk(a1.z, a1.z), pk(a1.w, a1.w) };
#pragma unroll
            for (int i = 0; i < 8; ++i)
#pragma unroll
                for (int jp = 0; jp < 4; ++jp)
                    ffma2(acc2[i][jp], ad[i], wp[jp]);
        }

        // stage prefetched tile into the idle buffer (safe: its readers
        // finished before the sync that opened THIS iteration)
        if (it < 31) {
            As[nxt][kq0 + 0][r0] = pa0.x; As[nxt][kq0 + 1][r0] = pa0.y;
            As[nxt][kq0 + 2][r0] = pa0.z; As[nxt][kq0 + 3][r0] = pa0.w;
            As[nxt][kq0 + 0][r1] = pa1.x; As[nxt][kq0 + 1][r1] = pa1.y;
            As[nxt][kq0 + 2][r1] = pa1.z; As[nxt][kq0 + 3][r1] = pa1.w;
            Ws[nxt][kq0 + 0][r0] = pw0.x; Ws[nxt][kq0 + 1][r0] = pw0.y;
            Ws[nxt][kq0 + 2][r0] = pw0.z; Ws[nxt][kq0 + 3][r0] = pw0.w;
            Ws[nxt][kq0 + 0][r1] = pw1.x; Ws[nxt][kq0 + 1][r1] = pw1.y;
            Ws[nxt][kq0 + 2][r1] = pw1.z; Ws[nxt][kq0 + 3][r1] = pw1.w;
            __syncthreads();
        }
    }

    float bb[8];
#pragma unroll
    for (int j = 0; j < 8; ++j) {
        int n = n0 + tx * 8 + j;
        bb[j] = bias1[n] + (bias2 ? bias2[n] : 0.0f);
    }
#pragma unroll
    for (int i = 0; i < 8; ++i) {
        int m = m0 + ty * 8 + i;
        if (m < Mguard) {
            float* cp = C + (size_t)m * 2048 + n0 + tx * 8;
            float2 p0 = unpk(acc2[i][0]), p1 = unpk(acc2[i][1]);
            float2 p2 = unpk(acc2[i][2]), p3 = unpk(acc2[i][3]);
            float4 v0 = make_float4(p0.x + bb[0], p0.y + bb[1],
                                    p1.x + bb[2], p1.y + bb[3]);
            float4 v1 = make_float4(p2.x + bb[4], p2.y + bb[5],
                                    p3.x + bb[6], p3.y + bb[7]);
            *(float4*)cp       = v0;
            *(float4*)(cp + 4) = v1;
        }
    }
}

// ---------------------------------------------------------------------------
// Persistent LSTM layer: 128 blocks x 256 threads, single wave.
// Block bk owns h-cols [bk*4, bk*4+4); thread (b, jc) computes one cell.
// h pair-interleaved in smem; packed fma.rn.f32x2 dots.
// NEW: next-step xg LDGs issued BEFORE the grid barrier so their latency
// hides under the barrier spin + h-broadcast reload.
// Dynamic smem: hs[512*64] + Wsm[16*512] = 160 KB.
// ---------------------------------------------------------------------------
__global__ void lstm_layer(const float* __restrict__ xg,
                           const float* __restrict__ Whh,
                           float* __restrict__ xout)
{
    extern __shared__ float sm[];
    float* hs  = sm;              // [512*64] pair-interleaved
    float* Wsm = sm + HID * NB;   // [16*512] layout [(g*4+jc)*512 + k]

    const int tid = threadIdx.x;
    const int b   = tid & 63;
    const int jc  = tid >> 6;
    const int bk  = blockIdx.x;
    const int j   = bk * 4 + jc;

    // Load W_hh slice (gate rows g*512 + bk*4 + jj), vectorized
    for (int idx = tid; idx < 16 * 128; idx += 256) {
        int rl = idx >> 7;            // 0..15 local row
        int k4 = idx & 127;
        int g  = rl >> 2, jj = rl & 3;
        ((float4*)Wsm)[rl * 128 + k4] =
            ((const float4*)Whh)[(size_t)(g * 512 + bk * 4 + jj) * 128 + k4];
    }
    // h0 = 0
    for (int idx = tid; idx < HID * NB / 4; idx += 256)
        ((float4*)hs)[idx] = make_float4(0.f, 0.f, 0.f, 0.f);
    __syncthreads();

    const float* wi = Wsm + (0 * 4 + jc) * 512;
    const float* wf = Wsm + (1 * 4 + jc) * 512;
    const float* wg = Wsm + (2 * 4 + jc) * 512;
    const float* wo = Wsm + (3 * 4 + jc) * 512;
    const ull* hp = (const ull*)hs;   // hp[t2*64 + b] = (h[2t2], h[2t2+1])

    // h write target (pair-interleaved): [(j>>1)*128 + b*2 + (j&1)]
    const int hoff = (j >> 1) * 128 + b * 2 + (j & 1);

    // preload step-0 gate inputs
    size_t base0 = ((size_t)0 * 64 + b) * 2048 + (size_t)j;
    float xi  = xg[base0];
    float xf  = xg[base0 + 512];
    float xgg = xg[base0 + 1024];
    float xo  = xg[base0 + 1536];

    float c = 0.f;
    for (int t = 0; t < TSTEPS; ++t) {
        ull ai2 = 0ull, af2 = 0ull, ag2 = 0ull, ao2 = 0ull;
#pragma unroll 4
        for (int k4 = 0; k4 < 128; ++k4) {
            float4 vi = ((const float4*)wi)[k4];
            float4 vf = ((const float4*)wf)[k4];
            float4 vg = ((const float4*)wg)[k4];
            float4 vo = ((const float4*)wo)[k4];
            ull h01 = hp[(2 * k4) * 64 + b];        // (h[4k4],   h[4k4+1])
            ull h23 = hp[(2 * k4 + 1) * 64 + b];    // (h[4k4+2], h[4k4+3])
            ffma2(ai2, h01, pk(vi.x, vi.y)); ffma2(ai2, h23, pk(vi.z, vi.w));
            ffma2(af2, h01, pk(vf.x, vf.y)); ffma2(af2, h23, pk(vf.z, vf.w));
            ffma2(ag2, h01, pk(vg.x, vg.y)); ffma2(ag2, h23, pk(vg.z, vg.w));
            ffma2(ao2, h01, pk(vo.x, vo.y)); ffma2(ao2, h23, pk(vo.z, vo.w));
        }
        float ai = psum(ai2), af = psum(af2), ag = psum(ag2), ao = psum(ao2);

        float I = 1.f / (1.f + expf(-(xi + ai)));
        float F = 1.f / (1.f + expf(-(xf + af)));
        float G = tanhf(xgg + ag);
        float O = 1.f / (1.f + expf(-(xo + ao)));
        c = F * c + I * G;
        float h = O * tanhf(c);

        xout[((size_t)t * 64 + b) * 512 + j] = h;
        int wb = (t + 1) & 1;
        g_hbuf[wb][hoff] = h;

        // prefetch next step's gate inputs (latency hidden by barrier+reload)
        if (t + 1 < TSTEPS) {
            size_t nb_ = ((size_t)(t + 1) * 64 + b) * 2048 + (size_t)j;
            xi  = xg[nb_];
            xf  = xg[nb_ + 512];
            xgg = xg[nb_ + 1024];
            xo  = xg[nb_ + 1536];
        }

        // ---- grid barrier (monotonic generation; replay/launch safe) ----
        __syncthreads();
        if (tid == 0) {
            unsigned gen = *(volatile unsigned*)&g_bar_gen;
            __threadfence();
            if (atomicAdd(&g_bar_cnt, 1u) == gridDim.x - 1u) {
                g_bar_cnt = 0;
                __threadfence();
                *(volatile unsigned*)&g_bar_gen = gen + 1u;
            } else {
                while (*(volatile unsigned*)&g_bar_gen == gen) { }
            }
            __threadfence();
        }
        __syncthreads();

        // reload full h into smem (same pair-interleaved layout: straight copy)
        const float4* src = (const float4*)g_hbuf[wb];
        for (int idx = tid; idx < HID * NB / 4; idx += 256)
            ((float4*)hs)[idx] = src[idx];
        __syncthreads();
    }
}

// ---------------------------------------------------------------------------
// threefry2x32 (JAX), key = (0, 1)
// ---------------------------------------------------------------------------
__device__ __forceinline__ void threefry01(uint32_t x0, uint32_t x1,
                                           uint32_t& o0, uint32_t& o1)
{
    const uint32_t k0 = 0u, k1 = 1u;
    const uint32_t k2 = 0x1BD11BDAu ^ k0 ^ k1;   // 0x1BD11BDB
    x0 += k0; x1 += k1;
#define TFR(r) { x0 += x1; x1 = (x1 << (r)) | (x1 >> (32 - (r))); x1 ^= x0; }
    TFR(13) TFR(15) TFR(26) TFR(6)
    x0 += k1; x1 += k2 + 1u;
    TFR(17) TFR(29) TFR(16) TFR(24)
    x0 += k2; x1 += k0 + 2u;
    TFR(13) TFR(15) TFR(26) TFR(6)
    x0 += k0; x1 += k1 + 3u;
    TFR(17) TFR(29) TFR(16) TFR(24)
    x0 += k1; x1 += k2 + 4u;
    TFR(13) TFR(15) TFR(26) TFR(6)
    x0 += k2; x1 += k0 + 5u;
#undef TFR
    o0 = x0; o1 = x1;
}

// JAX gumbel: u = bitcast(bits>>9 | 0x3f800000) - 1; u = max(u, tiny);
// g = -log(-log(u)).  Accurate logf required (fast-log tail error flips argmax).
__device__ __forceinline__ float gumbelf(uint32_t bits)
{
    float u = __uint_as_float((bits >> 9) | 0x3f800000u) - 1.0f;
    u = fmaxf(u, 1.17549435e-38f);
    return -logf(-logf(u));
}

// Partitionable threefry random_bits (jax/_src/prng.py):
//   bits1, bits2 = threefry2x32(key, counts_hi=0, counts_lo=i)
//   bit_width < 64: convert(bits1 ^ bits2)   <-- XOR of both output words
// One block per (t,b) row; 256 threads scan the 2048-vocab gumbel-argmax.
__global__ void sample_kernel(const float* __restrict__ logits,
                              float* outF, int* outI, int asInt)
{
    const int r = blockIdx.x;
    const int tid = threadIdx.x;

    float best = -3.4e38f;
    int bidx = 0;
    for (int v = tid; v < VOCAB; v += 256) {
        uint32_t i = (uint32_t)r * 2048u + (uint32_t)v;   // linear index < 2^32
        uint32_t o0, o1;
        threefry01(0u, i, o0, o1);
        float val = logits[(size_t)r * 2048 + v] + gumbelf(o0 ^ o1);
        if (val > best) { best = val; bidx = v; }   // strided v increasing -> first idx
    }

    __shared__ float svv[256];
    __shared__ int   sii[256];
    svv[tid] = best; sii[tid] = bidx;
    __syncthreads();
    for (int s = 128; s > 0; s >>= 1) {
        if (tid < s) {
            float v2 = svv[tid + s]; int i2 = sii[tid + s];
            float v1 = svv[tid];     int i1 = sii[tid];
            if (v2 > v1 || (v2 == v1 && i2 < i1)) { svv[tid] = v2; sii[tid] = i2; }
        }
        __syncthreads();
    }
    if (tid == 0) {
        if (asInt) outI[r] = sii[0];
        else       outF[r] = (float)sii[0];
    }
}

// ---------------------------------------------------------------------------
// Launch
// ---------------------------------------------------------------------------
extern "C" void kernel_launch(void* const* d_in, const int* in_sizes, int n_in,
                              void* d_out, int out_size)
{
    const int*   tok  = (const int*)  d_in[0];
    const float* emb  = (const float*)d_in[1];
    const float* Wih  = (const float*)d_in[2];
    const float* Whh  = (const float*)d_in[3];
    const float* bih  = (const float*)d_in[4];
    const float* bhh  = (const float*)d_in[5];
    const float* Wout = (const float*)d_in[6];
    const float* bout = (const float*)d_in[7];

    void* p;
    cudaGetSymbolAddress(&p, g_x);   float* xbuf  = (float*)p;
    cudaGetSymbolAddress(&p, g_xg);  float* xgbuf = (float*)p;

    cudaFuncSetAttribute(lstm_layer,
                         cudaFuncAttributeMaxDynamicSharedMemorySize, 164 * 1024);

    embed_kernel<<<MPAD * 128 / 256, 256>>>(tok, emb, xbuf);

    dim3 gg(GATES / 128, MPAD / 128);
    for (int l = 0; l < 3; ++l) {
        gemm_bias<<<gg, 256>>>(xbuf, Wih + (size_t)l * GATES * HID,
                               bih + l * GATES, bhh + l * GATES, xgbuf, MPAD);
        lstm_layer<<<128, 256, 163840>>>(xgbuf, Whh + (size_t)l * GATES * HID, xbuf);
    }

    // Output dispatch: tuple (indices, logits) flattened is the expected case.
    float* logitsPtr;
    int mode;                               // 0 full, 1 logits-only, 2 int idx
    if (out_size == MREAL + MREAL * VOCAB) { mode = 0; logitsPtr = (float*)d_out + MREAL; }
    else if (out_size == MREAL)            { mode = 2; logitsPtr = xgbuf; }
    else                                   { mode = 1; logitsPtr = (float*)d_out; }

    gemm_bias<<<gg, 256>>>(xbuf, Wout, bout, nullptr, logitsPtr, MREAL);

    if (mode == 0)
        sample_kernel<<<MREAL, 256>>>(logitsPtr, (float*)d_out, nullptr, 0);
    else if (mode == 2)
        sample_kernel<<<MREAL, 256>>>(logitsPtr, nullptr, (int*)d_out, 1);
}

// round 16
// speedup vs baseline: 1.0857x; 1.0314x over previous
#include <cuda_runtime.h>
#include <cstdint>
#include <math.h>

// Problem: V=2048, E=512, H=512, L=3, T=512, B=64 -> steps = 511
#define TSTEPS   511
#define NB       64
#define HID      512
#define GATES    2048
#define MREAL    32704            // 511*64
#define MPAD     32768            // padded rows (zeros)
#define VOCAB    2048

typedef unsigned long long ull;

// ---------------------------------------------------------------------------
// Packed f32x2 helpers (sm_103a). R14 finding: FFMA2 is DOUBLE-RATE
// (GEMM measured at 47 TF/s > 38 TF/s plain-FFMA ceiling).
// ---------------------------------------------------------------------------
__device__ __forceinline__ void ffma2(ull& d, ull a, ull b) {
    asm("fma.rn.f32x2 %0, %1, %2, %0;" : "+l"(d) : "l"(a), "l"(b));
}
__device__ __forceinline__ ull pk(float x, float y) {
    ull r; asm("mov.b64 %0, {%1, %2};" : "=l"(r) : "f"(x), "f"(y)); return r;
}
__device__ __forceinline__ float2 unpk(ull p) {
    float x, y; asm("mov.b64 {%0, %1}, %2;" : "=f"(x), "=f"(y) : "l"(p));
    return make_float2(x, y);
}
__device__ __forceinline__ float psum(ull p) {
    float2 v = unpk(p); return v.x + v.y;
}
// 128-bit shared load directly into two packed f32x2 operands (no pack movs)
__device__ __forceinline__ void lds2(ull& a, ull& b, uint32_t addr) {
    asm volatile("ld.shared.v2.b64 {%0,%1}, [%2];"
                 : "=l"(a), "=l"(b) : "r"(addr));
}

// ---------------------------------------------------------------------------
// Static scratch (no allocations anywhere)
// ---------------------------------------------------------------------------
__device__ float g_x [(size_t)MPAD * HID];    //  64 MB layer activations
__device__ float g_xg[(size_t)MPAD * GATES];  // 256 MB input gates / logits stage
// h state double buffer, quad-interleaved: h[k][b] at [(k>>2)*256 + b*4 + (k&3)]
__device__ float g_hbuf[2][HID * NB];
__device__ unsigned g_bar_cnt = 0;            // grid barrier (monotonic gen)
__device__ unsigned g_bar_gen = 0;

// ---------------------------------------------------------------------------
// Embedding gather: x[m][:] = emb[tok[m]][:], zero for pad rows
// ---------------------------------------------------------------------------
__global__ void embed_kernel(const int* __restrict__ tok,
                             const float* __restrict__ emb,
                             float* __restrict__ x)
{
    int idx = blockIdx.x * blockDim.x + threadIdx.x;  // over MPAD*128 float4
    int m  = idx >> 7;
    int e4 = idx & 127;
    float4 v = make_float4(0.f, 0.f, 0.f, 0.f);
    if (m < MREAL) {
        int t = tok[m];
        v = ((const float4*)emb)[(size_t)t * 128 + e4];
    }
    ((float4*)x)[(size_t)m * 128 + e4] = v;
}

// ---------------------------------------------------------------------------
// GEMM + bias (unchanged from R14 pass): BM=BN=128, BK=16, double-buffered,
// packed f32x2 accumulators, stride 136.
// ---------------------------------------------------------------------------
__global__ __launch_bounds__(256, 2)
void gemm_bias(const float* __restrict__ A, const float* __restrict__ W,
               const float* __restrict__ bias1, const float* __restrict__ bias2,
               float* __restrict__ C, int Mguard)
{
    __shared__ float As[2][16][136];
    __shared__ float Ws[2][16][136];
    const int tid = threadIdx.x;
    const int tx = tid & 15;
    const int ty = tid >> 4;
    const int n0 = blockIdx.x * 128;
    const int m0 = blockIdx.y * 128;

    ull acc2[8][4];
#pragma unroll
    for (int i = 0; i < 8; ++i)
#pragma unroll
        for (int jp = 0; jp < 4; ++jp) acc2[i][jp] = 0ull;

    const float* Ap = A + (size_t)m0 * 512;
    const float* Wp = W + (size_t)n0 * 512;

    const int r0  = tid >> 2;
    const int r1  = (tid + 256) >> 2;
    const int kq0 = (tid & 3) << 2;

    float4 pa0 = *(const float4*)(Ap + (size_t)r0 * 512 + kq0);
    float4 pa1 = *(const float4*)(Ap + (size_t)r1 * 512 + kq0);
    float4 pw0 = *(const float4*)(Wp + (size_t)r0 * 512 + kq0);
    float4 pw1 = *(const float4*)(Wp + (size_t)r1 * 512 + kq0);

    As[0][kq0 + 0][r0] = pa0.x; As[0][kq0 + 1][r0] = pa0.y;
    As[0][kq0 + 2][r0] = pa0.z; As[0][kq0 + 3][r0] = pa0.w;
    As[0][kq0 + 0][r1] = pa1.x; As[0][kq0 + 1][r1] = pa1.y;
    As[0][kq0 + 2][r1] = pa1.z; As[0][kq0 + 3][r1] = pa1.w;
    Ws[0][kq0 + 0][r0] = pw0.x; Ws[0][kq0 + 1][r0] = pw0.y;
    Ws[0][kq0 + 2][r0] = pw0.z; Ws[0][kq0 + 3][r0] = pw0.w;
    Ws[0][kq0 + 0][r1] = pw1.x; Ws[0][kq0 + 1][r1] = pw1.y;
    Ws[0][kq0 + 2][r1] = pw1.z; Ws[0][kq0 + 3][r1] = pw1.w;
    __syncthreads();

    for (int it = 0; it < 32; ++it) {
        const int cur = it & 1;
        const int nxt = cur ^ 1;

        if (it < 31) {
            int kn = (it + 1) * 16 + kq0;
            pa0 = *(const float4*)(Ap + (size_t)r0 * 512 + kn);
            pa1 = *(const float4*)(Ap + (size_t)r1 * 512 + kn);
            pw0 = *(const float4*)(Wp + (size_t)r0 * 512 + kn);
            pw1 = *(const float4*)(Wp + (size_t)r1 * 512 + kn);
        }

#pragma unroll
        for (int kk = 0; kk < 16; ++kk) {
            float4 a0 = *(const float4*)&As[cur][kk][ty * 8];
            float4 a1 = *(const float4*)&As[cur][kk][ty * 8 + 4];
            float4 w0 = *(const float4*)&Ws[cur][kk][tx * 8];
            float4 w1 = *(const float4*)&Ws[cur][kk][tx * 8 + 4];
            ull wp[4] = { pk(w0.x, w0.y), pk(w0.z, w0.w),
                          pk(w1.x, w1.y), pk(w1.z, w1.w) };
            ull ad[8] = { pk(a0.x, a0.x), pk(a0.y, a0.y),
                          pk(a0.z, a0.z), pk(a0.w, a0.w),
                          pk(a1.x, a1.x), pk(a1.y, a1.y),
                          pk(a1.z, a1.z), pk(a1.w, a1.w) };
#pragma unroll
            for (int i = 0; i < 8; ++i)
#pragma unroll
                for (int jp = 0; jp < 4; ++jp)
                    ffma2(acc2[i][jp], ad[i], wp[jp]);
        }

        if (it < 31) {
            As[nxt][kq0 + 0][r0] = pa0.x; As[nxt][kq0 + 1][r0] = pa0.y;
            As[nxt][kq0 + 2][r0] = pa0.z; As[nxt][kq0 + 3][r0] = pa0.w;
            As[nxt][kq0 + 0][r1] = pa1.x; As[nxt][kq0 + 1][r1] = pa1.y;
            As[nxt][kq0 + 2][r1] = pa1.z; As[nxt][kq0 + 3][r1] = pa1.w;
            Ws[nxt][kq0 + 0][r0] = pw0.x; Ws[nxt][kq0 + 1][r0] = pw0.y;
            Ws[nxt][kq0 + 2][r0] = pw0.z; Ws[nxt][kq0 + 3][r0] = pw0.w;
            Ws[nxt][kq0 + 0][r1] = pw1.x; Ws[nxt][kq0 + 1][r1] = pw1.y;
            Ws[nxt][kq0 + 2][r1] = pw1.z; Ws[nxt][kq0 + 3][r1] = pw1.w;
            __syncthreads();
        }
    }

    float bb[8];
#pragma unroll
    for (int j = 0; j < 8; ++j) {
        int n = n0 + tx * 8 + j;
        bb[j] = bias1[n] + (bias2 ? bias2[n] : 0.0f);
    }
#pragma unroll
    for (int i = 0; i < 8; ++i) {
        int m = m0 + ty * 8 + i;
        if (m < Mguard) {
            float* cp = C + (size_t)m * 2048 + n0 + tx * 8;
            float2 p0 = unpk(acc2[i][0]), p1 = unpk(acc2[i][1]);
            float2 p2 = unpk(acc2[i][2]), p3 = unpk(acc2[i][3]);
            float4 v0 = make_float4(p0.x + bb[0], p0.y + bb[1],
                                    p1.x + bb[2], p1.y + bb[3]);
            float4 v1 = make_float4(p2.x + bb[4], p2.y + bb[5],
                                    p3.x + bb[6], p3.y + bb[7]);
            *(float4*)cp       = v0;
            *(float4*)(cp + 4) = v1;
        }
    }
}

// ---------------------------------------------------------------------------
// Persistent LSTM layer, RE-TILED (R15):
// 128 blocks = 4 b-groups x 32 j-groups. Block = 16 b x 16 j.
//   smem: hq float4[128][16] (h quad-interleaved, 32 KB)
//       + Wsm float4[128 k4][4 gate][16 j] (j fastest, 128 KB) = 160 KB.
// Warp = 8b x 4j (lane: jl=l&3, bl=l>>2). Per k4 per warp:
//   1x ld.shared.v2.b64 for h (8 distinct lanes, 128B, 1 wavefront)
//   4x ld.shared.v2.b64 for w (4 distinct j, 64B each, 1 wavefront)
//   8x ffma2  (4 gates x 2)
// h-broadcast per step: 32 KB/block (was 128 KB) -> 4 MB/step through L2.
// ---------------------------------------------------------------------------
__global__ void lstm_layer(const float* __restrict__ xg,
                           const float* __restrict__ Whh,
                           float* __restrict__ xout)
{
    extern __shared__ float sm[];
    float* hs  = sm;                 // float4[128][16]  = 32 KB
    float* Wsm = sm + 8192;          // float4[128][4][16] = 128 KB

    const int tid = threadIdx.x;
    const int bk  = blockIdx.x;
    const int b0  = (bk & 3) * 16;
    const int j0  = (bk >> 2) * 16;

    const int w   = tid >> 5;
    const int l   = tid & 31;
    const int jl  = (w & 3) * 4 + (l & 3);     // 0..15
    const int bl  = (w >> 2) * 8 + (l >> 2);   // 0..15
    const int j   = j0 + jl;
    const int b   = b0 + bl;

    // Load W_hh slice: Wsm[k4][g][j2] = Whh[(g*512 + j0 + j2)][4k4..4k4+3]
    // (k4 fastest across tid -> coalesced gmem reads)
    for (int idx = tid; idx < 128 * 4 * 16; idx += 256) {
        int k4 = idx & 127;
        int g  = (idx >> 7) & 3;
        int j2 = idx >> 9;               // 0..15
        ((float4*)Wsm)[(k4 * 4 + g) * 16 + j2] =
            ((const float4*)Whh)[(size_t)(g * 512 + j0 + j2) * 128 + k4];
    }
    // h0 = 0
    for (int idx = tid; idx < 2048; idx += 256)
        ((float4*)hs)[idx] = make_float4(0.f, 0.f, 0.f, 0.f);
    __syncthreads();

    // shared-space byte addresses for asm LDS
    uint32_t smem_base;
    asm("{ .reg .u64 t; cvta.to.shared.u64 t, %1; cvt.u32.u64 %0, t; }"
        : "=r"(smem_base) : "l"(sm));
    const uint32_t haddr0 = smem_base + (uint32_t)bl * 16u;           // +k4*256
    const uint32_t waddr0 = smem_base + 32768u + (uint32_t)jl * 16u;  // +k4*1024+g*256

    // h output slot (quad-interleaved global layout)
    const int hoff = (j >> 2) * 256 + b * 4 + (j & 3);

    // preload step-0 gate inputs
    size_t base0 = ((size_t)b) * 2048 + (size_t)j;
    float xi  = xg[base0];
    float xf  = xg[base0 + 512];
    float xgg = xg[base0 + 1024];
    float xo  = xg[base0 + 1536];

    float c = 0.f;
    for (int t = 0; t < TSTEPS; ++t) {
        ull a0 = 0ull, a1 = 0ull, a2 = 0ull, a3 = 0ull;
#pragma unroll 8
        for (int k4 = 0; k4 < 128; ++k4) {
            ull h01, h23, w01, w23;
            lds2(h01, h23, haddr0 + (uint32_t)k4 * 256u);
            lds2(w01, w23, waddr0 + (uint32_t)k4 * 1024u);
            ffma2(a0, h01, w01); ffma2(a0, h23, w23);
            lds2(w01, w23, waddr0 + (uint32_t)k4 * 1024u + 256u);
            ffma2(a1, h01, w01); ffma2(a1, h23, w23);
            lds2(w01, w23, waddr0 + (uint32_t)k4 * 1024u + 512u);
            ffma2(a2, h01, w01); ffma2(a2, h23, w23);
            lds2(w01, w23, waddr0 + (uint32_t)k4 * 1024u + 768u);
            ffma2(a3, h01, w01); ffma2(a3, h23, w23);
        }
        float ai = psum(a0), af = psum(a1), ag = psum(a2), ao = psum(a3);

        float I = 1.f / (1.f + expf(-(xi + ai)));
        float F = 1.f / (1.f + expf(-(xf + af)));
        float G = tanhf(xgg + ag);
        float O = 1.f / (1.f + expf(-(xo + ao)));
        c = F * c + I * G;
        float h = O * tanhf(c);

        xout[((size_t)t * 64 + b) * 512 + j] = h;
        int wb = (t + 1) & 1;
        g_hbuf[wb][hoff] = h;

        // prefetch next step's gate inputs (hidden under barrier + reload)
        if (t + 1 < TSTEPS) {
            size_t nb_ = ((size_t)(t + 1) * 64 + b) * 2048 + (size_t)j;
            xi  = xg[nb_];
            xf  = xg[nb_ + 512];
            xgg = xg[nb_ + 1024];
            xo  = xg[nb_ + 1536];
        }

        // ---- grid barrier (monotonic generation; replay/launch safe) ----
        __syncthreads();
        if (tid == 0) {
            unsigned gen = *(volatile unsigned*)&g_bar_gen;
            __threadfence();
            if (atomicAdd(&g_bar_cnt, 1u) == gridDim.x - 1u) {
                g_bar_cnt = 0;
                __threadfence();
                *(volatile unsigned*)&g_bar_gen = gen + 1u;
            } else {
                while (*(volatile unsigned*)&g_bar_gen == gen) { }
            }
            __threadfence();
        }
        __syncthreads();

        // reload h tile: this block's 16 batches, all 512 k (32 KB)
        {
            const float4* src = (const float4*)g_hbuf[wb];
            for (int idx = tid; idx < 2048; idx += 256) {
                int k4  = idx >> 4;
                int bl2 = idx & 15;
                ((float4*)hs)[idx] = src[k4 * 64 + b0 + bl2];
            }
        }
        __syncthreads();
    }
}

// ---------------------------------------------------------------------------
// threefry2x32 (JAX), key = (0, 1)
// ---------------------------------------------------------------------------
__device__ __forceinline__ void threefry01(uint32_t x0, uint32_t x1,
                                           uint32_t& o0, uint32_t& o1)
{
    const uint32_t k0 = 0u, k1 = 1u;
    const uint32_t k2 = 0x1BD11BDAu ^ k0 ^ k1;   // 0x1BD11BDB
    x0 += k0; x1 += k1;
#define TFR(r) { x0 += x1; x1 = (x1 << (r)) | (x1 >> (32 - (r))); x1 ^= x0; }
    TFR(13) TFR(15) TFR(26) TFR(6)
    x0 += k1; x1 += k2 + 1u;
    TFR(17) TFR(29) TFR(16) TFR(24)
    x0 += k2; x1 += k0 + 2u;
    TFR(13) TFR(15) TFR(26) TFR(6)
    x0 += k0; x1 += k1 + 3u;
    TFR(17) TFR(29) TFR(16) TFR(24)
    x0 += k1; x1 += k2 + 4u;
    TFR(13) TFR(15) TFR(26) TFR(6)
    x0 += k2; x1 += k0 + 5u;
#undef TFR
    o0 = x0; o1 = x1;
}

// JAX gumbel: u = bitcast(bits>>9 | 0x3f800000) - 1; u = max(u, tiny);
// g = -log(-log(u)).  Accurate logf required (fast-log tail error flips argmax).
__device__ __forceinline__ float gumbelf(uint32_t bits)
{
    float u = __uint_as_float((bits >> 9) | 0x3f800000u) - 1.0f;
    u = fmaxf(u, 1.17549435e-38f);
    return -logf(-logf(u));
}

// Partitionable threefry random_bits (jax/_src/prng.py):
//   bits1, bits2 = threefry2x32(key, counts_hi=0, counts_lo=i)
//   bit_width < 64: convert(bits1 ^ bits2)   <-- XOR of both output words
// One block per (t,b) row; 256 threads scan the 2048-vocab gumbel-argmax.
__global__ void sample_kernel(const float* __restrict__ logits,
                              float* outF, int* outI, int asInt)
{
    const int r = blockIdx.x;
    const int tid = threadIdx.x;

    float best = -3.4e38f;
    int bidx = 0;
    for (int v = tid; v < VOCAB; v += 256) {
        uint32_t i = (uint32_t)r * 2048u + (uint32_t)v;   // linear index < 2^32
        uint32_t o0, o1;
        threefry01(0u, i, o0, o1);
        float val = logits[(size_t)r * 2048 + v] + gumbelf(o0 ^ o1);
        if (val > best) { best = val; bidx = v; }   // strided v increasing -> first idx
    }

    __shared__ float svv[256];
    __shared__ int   sii[256];
    svv[tid] = best; sii[tid] = bidx;
    __syncthreads();
    for (int s = 128; s > 0; s >>= 1) {
        if (tid < s) {
            float v2 = svv[tid + s]; int i2 = sii[tid + s];
            float v1 = svv[tid];     int i1 = sii[tid];
            if (v2 > v1 || (v2 == v1 && i2 < i1)) { svv[tid] = v2; sii[tid] = i2; }
        }
        __syncthreads();
    }
    if (tid == 0) {
        if (asInt) outI[r] = sii[0];
        else       outF[r] = (float)sii[0];
    }
}

// ---------------------------------------------------------------------------
// Launch
// ---------------------------------------------------------------------------
extern "C" void kernel_launch(void* const* d_in, const int* in_sizes, int n_in,
                              void* d_out, int out_size)
{
    const int*   tok  = (const int*)  d_in[0];
    const float* emb  = (const float*)d_in[1];
    const float* Wih  = (const float*)d_in[2];
    const float* Whh  = (const float*)d_in[3];
    const float* bih  = (const float*)d_in[4];
    const float* bhh  = (const float*)d_in[5];
    const float* Wout = (const float*)d_in[6];
    const float* bout = (const float*)d_in[7];

    void* p;
    cudaGetSymbolAddress(&p, g_x);   float* xbuf  = (float*)p;
    cudaGetSymbolAddress(&p, g_xg);  float* xgbuf = (float*)p;

    cudaFuncSetAttribute(lstm_layer,
                         cudaFuncAttributeMaxDynamicSharedMemorySize, 164 * 1024);

    embed_kernel<<<MPAD * 128 / 256, 256>>>(tok, emb, xbuf);

    dim3 gg(GATES / 128, MPAD / 128);
    for (int l = 0; l < 3; ++l) {
        gemm_bias<<<gg, 256>>>(xbuf, Wih + (size_t)l * GATES * HID,
                               bih + l * GATES, bhh + l * GATES, xgbuf, MPAD);
        lstm_layer<<<128, 256, 163840>>>(xgbuf, Whh + (size_t)l * GATES * HID, xbuf);
    }

    // Output dispatch: tuple (indices, logits) flattened is the expected case.
    float* logitsPtr;
    int mode;                               // 0 full, 1 logits-only, 2 int idx
    if (out_size == MREAL + MREAL * VOCAB) { mode = 0; logitsPtr = (float*)d_out + MREAL; }
    else if (out_size == MREAL)            { mode = 2; logitsPtr = xgbuf; }
    else                                   { mode = 1; logitsPtr = (float*)d_out; }

    gemm_bias<<<gg, 256>>>(xbuf, Wout, bout, nullptr, logitsPtr, MREAL);

    if (mode == 0)
        sample_kernel<<<MREAL, 256>>>(logitsPtr, (float*)d_out, nullptr, 0);
    else if (mode == 2)
        sample_kernel<<<MREAL, 256>>>(logitsPtr, nullptr, (int*)d_out, 1);
}